// round 5
// baseline (speedup 1.0000x reference)
#include <cuda_runtime.h>
#include <cuda_fp16.h>
#include <cstdint>

#define BATCH 8
#define S1D 2048
#define S2D 2048
#define EDIM 1024
#define PDIM 1024

#define BM 128
#define BN 128
#define BK 64

// ---------------- scratch ----------------
__device__ __half g_inh[(size_t)3 * BATCH * S1D * EDIM];   // q,k,v fp16 (96 MB)
__device__ __half g_outh[(size_t)3 * BATCH * S1D * PDIM];  // projected q,k,v fp16 (96 MB)
__device__ __half g_wh[(size_t)PDIM * EDIM];               // 2 MB
__device__ __half g_scores[(size_t)BATCH * S1D * S2D];     // fp16 scaled scores (67 MB)
__device__ __half g_probs[(size_t)BATCH * S1D * S2D];      // 67 MB

__device__ __forceinline__ void mma16816(float c[4], const uint32_t a[4], const uint32_t b[2]) {
    asm volatile(
        "mma.sync.aligned.m16n8k16.row.col.f32.f16.f16.f32 "
        "{%0,%1,%2,%3}, {%4,%5,%6,%7}, {%8,%9}, {%0,%1,%2,%3};\n"
        : "+f"(c[0]), "+f"(c[1]), "+f"(c[2]), "+f"(c[3])
        : "r"(a[0]), "r"(a[1]), "r"(a[2]), "r"(a[3]), "r"(b[0]), "r"(b[1]));
}

__device__ __forceinline__ void cp16(__half* sptr, const __half* gptr) {
    uint32_t s = (uint32_t)__cvta_generic_to_shared(sptr);
    asm volatile("cp.async.cg.shared.global [%0], [%1], 16;\n" :: "r"(s), "l"(gptr));
}
#define CP_COMMIT() asm volatile("cp.async.commit_group;\n")

__device__ __forceinline__ uint32_t h2_as_u32(__half2 h) {
    return *reinterpret_cast<uint32_t*>(&h);
}

// =================================================================================
// Shared GEMM mainloop. Block 128x128, BK=64, 8 warps (warp tile 32x64), 3-stage
// cp.async pipeline. A: [M][K] fp16 k-major. B: NT: [N][K] k-major; NN: [K][N].
// Smem swizzle: 16B chunk c at row r placed at chunk (c ^ (r&7)) within 128B span.
// =================================================================================
template<int BNN>
__device__ __forceinline__ void gemm_main(const __half* __restrict__ A,
                                          const __half* __restrict__ B,
                                          int lda, int ldb, int m0, int n0, int KT,
                                          __half* sm, float c[2][8][4]) {
    const int tid = threadIdx.x;
    const int warp = tid >> 5, lane = tid & 31;
    const int wm = (warp & 3) * 32, wn = (warp >> 2) * 64;
    __half* As0 = sm;           // 3 x 8192 halves
    __half* Bs0 = sm + 24576;   // 3 x 8192 halves

    const int a_r = tid >> 3, a_c = tid & 7;       // A/B-NT: 128 rows x 8 chunks, 4 sweeps
    const int bn_r = tid >> 4, bn_c = tid & 15;    // B-NN: 64 rows x 16 chunks, 4 sweeps

#define LOAD_A(kt, buf) {                                                              \
        __half* S = As0 + (buf) * 8192;                                                \
        _Pragma("unroll")                                                              \
        for (int s = 0; s < 4; s++) {                                                  \
            int r = a_r + 32 * s;                                                      \
            cp16(S + r * 64 + ((a_c ^ (r & 7)) << 3),                                  \
                 A + (size_t)(m0 + r) * lda + (kt) * 64 + a_c * 8);                    \
        } }
#define LOAD_B(kt, buf) {                                                              \
        __half* S = Bs0 + (buf) * 8192;                                                \
        if (!BNN) {                                                                    \
            _Pragma("unroll")                                                          \
            for (int s = 0; s < 4; s++) {                                              \
                int r = a_r + 32 * s;                                                  \
                cp16(S + r * 64 + ((a_c ^ (r & 7)) << 3),                              \
                     B + (size_t)(n0 + r) * ldb + (kt) * 64 + a_c * 8);                \
            }                                                                          \
        } else {                                                                       \
            _Pragma("unroll")                                                          \
            for (int s = 0; s < 4; s++) {                                              \
                int r = bn_r + 16 * s;                                                 \
                int pc = (bn_c & 8) | ((bn_c & 7) ^ (r & 7));                          \
                cp16(S + r * 128 + (pc << 3),                                          \
                     B + (size_t)((kt) * 64 + r) * ldb + n0 + bn_c * 8);               \
            }                                                                          \
        } }

    LOAD_A(0, 0); LOAD_B(0, 0); CP_COMMIT();
    LOAD_A(1, 1); LOAD_B(1, 1); CP_COMMIT();

    for (int kt = 0; kt < KT; kt++) {
        const int buf = kt % 3;
        if (kt + 1 < KT) asm volatile("cp.async.wait_group 1;\n");
        else             asm volatile("cp.async.wait_group 0;\n");
        __syncthreads();
        if (kt + 2 < KT) {
            const int nb = (kt + 2) % 3;
            LOAD_A(kt + 2, nb); LOAD_B(kt + 2, nb); CP_COMMIT();
        }

        const __half* As = As0 + buf * 8192;
        const __half* Bs = Bs0 + buf * 8192;
#pragma unroll
        for (int kk = 0; kk < 64; kk += 16) {
            uint32_t a[2][4];
#pragma unroll
            for (int i = 0; i < 2; i++) {
                int row = wm + 16 * i + (lane & 15);
                int kc = (kk >> 3) + ((lane & 16) ? 1 : 0);
                uint32_t addr = (uint32_t)__cvta_generic_to_shared(
                    As + row * 64 + ((kc ^ (row & 7)) << 3));
                asm volatile("ldmatrix.sync.aligned.m8n8.x4.shared.b16 {%0,%1,%2,%3}, [%4];\n"
                             : "=r"(a[i][0]), "=r"(a[i][1]), "=r"(a[i][2]), "=r"(a[i][3])
                             : "r"(addr));
            }
            uint32_t b[8][2];
            if (!BNN) {
#pragma unroll
                for (int l = 0; l < 4; l++) {
                    int row = wn + 16 * l + (lane & 7) + ((lane & 16) ? 8 : 0);
                    int kc = (kk >> 3) + ((lane & 8) ? 1 : 0);
                    uint32_t addr = (uint32_t)__cvta_generic_to_shared(
                        Bs + row * 64 + ((kc ^ (row & 7)) << 3));
                    asm volatile("ldmatrix.sync.aligned.m8n8.x4.shared.b16 {%0,%1,%2,%3}, [%4];\n"
                                 : "=r"(b[2 * l][0]), "=r"(b[2 * l][1]),
                                   "=r"(b[2 * l + 1][0]), "=r"(b[2 * l + 1][1])
                                 : "r"(addr));
                }
            } else {
#pragma unroll
                for (int l = 0; l < 4; l++) {
                    int row = kk + (lane & 7) + ((lane & 8) ? 8 : 0);
                    int cc = ((wn + 16 * l) >> 3) + ((lane & 16) ? 1 : 0);
                    int pc = (cc & 8) | ((cc & 7) ^ (row & 7));
                    uint32_t addr = (uint32_t)__cvta_generic_to_shared(
                        Bs + row * 128 + (pc << 3));
                    asm volatile("ldmatrix.sync.aligned.m8n8.x4.trans.shared.b16 {%0,%1,%2,%3}, [%4];\n"
                                 : "=r"(b[2 * l][0]), "=r"(b[2 * l][1]),
                                   "=r"(b[2 * l + 1][0]), "=r"(b[2 * l + 1][1])
                                 : "r"(addr));
                }
            }
#pragma unroll
            for (int i = 0; i < 2; i++)
#pragma unroll
                for (int j = 0; j < 8; j++) mma16816(c[i][j], a[i], b[j]);
        }
    }
#undef LOAD_A
#undef LOAD_B
}

// ---------------- fp32 -> fp16 conversion ----------------
__global__ void __launch_bounds__(256) conv_kernel(const float* __restrict__ src,
                                                   __half* __restrict__ dst) {
    size_t i = ((size_t)blockIdx.x * 256 + threadIdx.x) * 8;
    float4 v0 = *(const float4*)(src + i);
    float4 v1 = *(const float4*)(src + i + 4);
    uint4 o;
    o.x = h2_as_u32(__floats2half2_rn(v0.x, v0.y));
    o.y = h2_as_u32(__floats2half2_rn(v0.z, v0.w));
    o.z = h2_as_u32(__floats2half2_rn(v1.x, v1.y));
    o.w = h2_as_u32(__floats2half2_rn(v1.z, v1.w));
    *(uint4*)(dst + i) = o;
}

// ---------------- projection: g_outh = g_inh @ W^T + bias (fp16 out) ----------------
__global__ void __launch_bounds__(256, 2) proj_kernel(const float* __restrict__ bias) {
    extern __shared__ __half sm[];
    const int m0 = blockIdx.y * BM, n0 = blockIdx.x * BN;
    float c[2][8][4] = {};
    gemm_main<0>(g_inh, g_wh, EDIM, EDIM, m0, n0, EDIM / BK, sm, c);

    const int lane = threadIdx.x & 31, warp = threadIdx.x >> 5;
    const int wm = (warp & 3) * 32, wn = (warp >> 2) * 64;
    const int g = lane >> 2, t = lane & 3;
#pragma unroll
    for (int i = 0; i < 2; i++)
#pragma unroll
        for (int j = 0; j < 8; j++) {
            int row = m0 + wm + 16 * i + g;
            int col = n0 + wn + 8 * j + 2 * t;
            float b0 = bias[col], b1 = bias[col + 1];
            *(__half2*)(g_outh + (size_t)row * PDIM + col) =
                __floats2half2_rn(c[i][j][0] + b0, c[i][j][1] + b1);
            *(__half2*)(g_outh + (size_t)(row + 8) * PDIM + col) =
                __floats2half2_rn(c[i][j][2] + b0, c[i][j][3] + b1);
        }
}

// ---------------- scores: fp16 = (Qp @ Kp^T) / 32 ----------------
__global__ void __launch_bounds__(256, 2) scores_kernel() {
    extern __shared__ __half sm[];
    const size_t z = blockIdx.z;
    const __half* A = g_outh + z * S1D * PDIM;
    const __half* B = g_outh + (size_t)BATCH * S1D * PDIM + z * S2D * PDIM;
    __half* C = g_scores + z * S1D * S2D;
    const int m0 = blockIdx.y * BM, n0 = blockIdx.x * BN;
    float c[2][8][4] = {};
    gemm_main<0>(A, B, PDIM, PDIM, m0, n0, PDIM / BK, sm, c);

    const int lane = threadIdx.x & 31, warp = threadIdx.x >> 5;
    const int wm = (warp & 3) * 32, wn = (warp >> 2) * 64;
    const int g = lane >> 2, t = lane & 3;
    const float SC = 0.03125f;
#pragma unroll
    for (int i = 0; i < 2; i++)
#pragma unroll
        for (int j = 0; j < 8; j++) {
            int row = m0 + wm + 16 * i + g;
            int col = n0 + wn + 8 * j + 2 * t;
            *(__half2*)(C + (size_t)row * S2D + col) =
                __floats2half2_rn(c[i][j][0] * SC, c[i][j][1] * SC);
            *(__half2*)(C + (size_t)(row + 8) * S2D + col) =
                __floats2half2_rn(c[i][j][2] * SC, c[i][j][3] * SC);
        }
}

// ---------------- softmax over last dim (2048), fp16 in -> fp16 probs ----------------
// exp computed with ex2.approx.f16x2 (h2exp2): halves MUFU ops vs fp32 expf.
__global__ void __launch_bounds__(256) softmax_kernel() {
    const size_t row = blockIdx.x;
    const __half* src = g_scores + row * S2D;
    __half* dst = g_probs + row * S2D;
    const int tid = threadIdx.x;
    const int lane = tid & 31, warp = tid >> 5;

    uint4 raw = *(const uint4*)(src + tid * 8);
    __half2 h[4];
    h[0] = *reinterpret_cast<__half2*>(&raw.x);
    h[1] = *reinterpret_cast<__half2*>(&raw.y);
    h[2] = *reinterpret_cast<__half2*>(&raw.z);
    h[3] = *reinterpret_cast<__half2*>(&raw.w);

    float2 x[4];
#pragma unroll
    for (int i = 0; i < 4; i++) x[i] = __half22float2(h[i]);

    float m = fmaxf(fmaxf(fmaxf(x[0].x, x[0].y), fmaxf(x[1].x, x[1].y)),
                    fmaxf(fmaxf(x[2].x, x[2].y), fmaxf(x[3].x, x[3].y)));
#pragma unroll
    for (int off = 16; off > 0; off >>= 1)
        m = fmaxf(m, __shfl_xor_sync(0xffffffffu, m, off));

    __shared__ float red[8];
    __shared__ float sbc;
    if (lane == 0) red[warp] = m;
    __syncthreads();
    if (warp == 0) {
        float v = (lane < 8) ? red[lane] : -1e30f;
#pragma unroll
        for (int off = 4; off > 0; off >>= 1)
            v = fmaxf(v, __shfl_xor_sync(0xffffffffu, v, off));
        if (lane == 0) sbc = v;
    }
    __syncthreads();
    m = sbc;

    const float L2E = 1.44269504f;
    __half2 e[4];
#pragma unroll
    for (int i = 0; i < 4; i++)
        e[i] = h2exp2(__floats2half2_rn((x[i].x - m) * L2E, (x[i].y - m) * L2E));

    float s = 0.0f;
#pragma unroll
    for (int i = 0; i < 4; i++) {
        float2 f = __half22float2(e[i]);
        s += f.x + f.y;
    }
#pragma unroll
    for (int off = 16; off > 0; off >>= 1)
        s += __shfl_xor_sync(0xffffffffu, s, off);
    __syncthreads();
    if (lane == 0) red[warp] = s;
    __syncthreads();
    if (warp == 0) {
        float v = (lane < 8) ? red[lane] : 0.0f;
#pragma unroll
        for (int off = 4; off > 0; off >>= 1)
            v += __shfl_xor_sync(0xffffffffu, v, off);
        if (lane == 0) sbc = v;
    }
    __syncthreads();
    __half2 iv = __float2half2_rn(1.0f / sbc);

    uint4 o;
    __half2 p0 = __hmul2(e[0], iv), p1 = __hmul2(e[1], iv);
    __half2 p2 = __hmul2(e[2], iv), p3 = __hmul2(e[3], iv);
    o.x = h2_as_u32(p0); o.y = h2_as_u32(p1); o.z = h2_as_u32(p2); o.w = h2_as_u32(p3);
    *(uint4*)(dst + tid * 8) = o;
}

// ---------------- output: O = probs @ Vp  (NN gemm via ldmatrix.trans) ----------------
__global__ void __launch_bounds__(256, 2) out_kernel(float* __restrict__ OUT) {
    extern __shared__ __half sm[];
    const size_t z = blockIdx.z;
    const __half* A = g_probs + z * S1D * S2D;
    const __half* B = g_outh + (size_t)2 * BATCH * S1D * PDIM + z * S2D * PDIM;
    float* C = OUT + z * S1D * PDIM;
    const int m0 = blockIdx.y * BM, n0 = blockIdx.x * BN;
    float c[2][8][4] = {};
    gemm_main<1>(A, B, S2D, PDIM, m0, n0, S2D / BK, sm, c);

    const int lane = threadIdx.x & 31, warp = threadIdx.x >> 5;
    const int wm = (warp & 3) * 32, wn = (warp >> 2) * 64;
    const int g = lane >> 2, t = lane & 3;
#pragma unroll
    for (int i = 0; i < 2; i++)
#pragma unroll
        for (int j = 0; j < 8; j++) {
            int row = m0 + wm + 16 * i + g;
            int col = n0 + wn + 8 * j + 2 * t;
            *(float2*)(C + (size_t)row * PDIM + col) = make_float2(c[i][j][0], c[i][j][1]);
            *(float2*)(C + (size_t)(row + 8) * PDIM + col) = make_float2(c[i][j][2], c[i][j][3]);
        }
}

// ---------------- launch ----------------
extern "C" void kernel_launch(void* const* d_in, const int* in_sizes, int n_in,
                              void* d_out, int out_size) {
    const float* q = (const float*)d_in[0];
    const float* k = (const float*)d_in[1];
    const float* v = (const float*)d_in[2];
    const float* W = (const float*)d_in[3];
    const float* b = (const float*)d_in[4];
    float* out = (float*)d_out;

    static bool attr_done = false;
    if (!attr_done) {
        cudaFuncSetAttribute(proj_kernel, cudaFuncAttributeMaxDynamicSharedMemorySize, 98304);
        cudaFuncSetAttribute(scores_kernel, cudaFuncAttributeMaxDynamicSharedMemorySize, 98304);
        cudaFuncSetAttribute(out_kernel, cudaFuncAttributeMaxDynamicSharedMemorySize, 98304);
        attr_done = true;
    }

    __half* inh;
    __half* wh;
    cudaGetSymbolAddress((void**)&inh, g_inh);
    cudaGetSymbolAddress((void**)&wh, g_wh);

    const size_t NT = (size_t)BATCH * S1D * EDIM;  // 16.7M per tensor
    conv_kernel<<<NT / (256 * 8), 256>>>(q, inh);
    conv_kernel<<<NT / (256 * 8), 256>>>(k, inh + NT);
    conv_kernel<<<NT / (256 * 8), 256>>>(v, inh + 2 * NT);
    conv_kernel<<<(PDIM * EDIM) / (256 * 8), 256>>>(W, wh);

    dim3 gproj(PDIM / BN, (3 * BATCH * S1D) / BM);  // 8 x 384
    proj_kernel<<<gproj, 256, 98304>>>(b);

    dim3 gs(S2D / BN, S1D / BM, BATCH);  // 16 x 16 x 8
    scores_kernel<<<gs, 256, 98304>>>();

    softmax_kernel<<<BATCH * S1D, 256>>>();

    dim3 go(PDIM / BN, S1D / BM, BATCH);  // 8 x 16 x 8
    out_kernel<<<go, 256, 98304>>>(out);
}

// round 9
// speedup vs baseline: 1.0257x; 1.0257x over previous
#include <cuda_runtime.h>
#include <cuda_fp16.h>
#include <cstdint>

#define BATCH 8
#define S1D 2048
#define S2D 2048
#define EDIM 1024
#define PDIM 1024

#define BM 128
#define BN 128
#define BK 64

// ---------------- scratch ----------------
__device__ __half g_inh[(size_t)3 * BATCH * S1D * EDIM];   // q,k,v fp16 (96 MB)
__device__ __half g_outh[(size_t)3 * BATCH * S1D * PDIM];  // projected q,k,v fp16 (96 MB)
__device__ __half g_wh[(size_t)PDIM * EDIM];               // 2 MB
__device__ __half g_probs[(size_t)BATCH * S1D * S2D];      // exp(scores) fp16 (67 MB)
__device__ float  g_rowsum[(size_t)BATCH * S1D];           // 64 KB

__device__ __forceinline__ void mma16816(float c[4], const uint32_t a[4], const uint32_t b[2]) {
    asm volatile(
        "mma.sync.aligned.m16n8k16.row.col.f32.f16.f16.f32 "
        "{%0,%1,%2,%3}, {%4,%5,%6,%7}, {%8,%9}, {%0,%1,%2,%3};\n"
        : "+f"(c[0]), "+f"(c[1]), "+f"(c[2]), "+f"(c[3])
        : "r"(a[0]), "r"(a[1]), "r"(a[2]), "r"(a[3]), "r"(b[0]), "r"(b[1]));
}

__device__ __forceinline__ void cp16(__half* sptr, const __half* gptr) {
    uint32_t s = (uint32_t)__cvta_generic_to_shared(sptr);
    asm volatile("cp.async.cg.shared.global [%0], [%1], 16;\n" :: "r"(s), "l"(gptr));
}
#define CP_COMMIT() asm volatile("cp.async.commit_group;\n")

__device__ __forceinline__ uint32_t h2_as_u32(__half2 h) {
    return *reinterpret_cast<uint32_t*>(&h);
}

// =================================================================================
// Shared GEMM mainloop. Block 128x128, BK=64, 8 warps (warp tile 32x64), 3-stage
// cp.async pipeline, fp32 accumulators. A: [M][K] fp16 k-major.
// B: NT: [N][K] k-major; NN: [K][N] n-major (ldmatrix.trans).
// Smem swizzle: 16B chunk c at row r placed at chunk (c ^ (r&7)) within 128B span.
// =================================================================================
template<int BNN>
__device__ __forceinline__ void gemm_main(const __half* __restrict__ A,
                                          const __half* __restrict__ B,
                                          int lda, int ldb, int m0, int n0, int KT,
                                          __half* sm, float c[2][8][4]) {
    const int tid = threadIdx.x;
    const int warp = tid >> 5, lane = tid & 31;
    const int wm = (warp & 3) * 32, wn = (warp >> 2) * 64;
    __half* As0 = sm;           // 3 x 8192 halves
    __half* Bs0 = sm + 24576;   // 3 x 8192 halves

    const int a_r = tid >> 3, a_c = tid & 7;
    const int bn_r = tid >> 4, bn_c = tid & 15;

#define LOAD_A(kt, buf) {                                                              \
        __half* S = As0 + (buf) * 8192;                                                \
        _Pragma("unroll")                                                              \
        for (int s = 0; s < 4; s++) {                                                  \
            int r = a_r + 32 * s;                                                      \
            cp16(S + r * 64 + ((a_c ^ (r & 7)) << 3),                                  \
                 A + (size_t)(m0 + r) * lda + (kt) * 64 + a_c * 8);                    \
        } }
#define LOAD_B(kt, buf) {                                                              \
        __half* S = Bs0 + (buf) * 8192;                                                \
        if (!BNN) {                                                                    \
            _Pragma("unroll")                                                          \
            for (int s = 0; s < 4; s++) {                                              \
                int r = a_r + 32 * s;                                                  \
                cp16(S + r * 64 + ((a_c ^ (r & 7)) << 3),                              \
                     B + (size_t)(n0 + r) * ldb + (kt) * 64 + a_c * 8);                \
            }                                                                          \
        } else {                                                                       \
            _Pragma("unroll")                                                          \
            for (int s = 0; s < 4; s++) {                                              \
                int r = bn_r + 16 * s;                                                 \
                int pc = (bn_c & 8) | ((bn_c & 7) ^ (r & 7));                          \
                cp16(S + r * 128 + (pc << 3),                                          \
                     B + (size_t)((kt) * 64 + r) * ldb + n0 + bn_c * 8);               \
            }                                                                          \
        } }

    LOAD_A(0, 0); LOAD_B(0, 0); CP_COMMIT();
    LOAD_A(1, 1); LOAD_B(1, 1); CP_COMMIT();

    for (int kt = 0; kt < KT; kt++) {
        const int buf = kt % 3;
        if (kt + 1 < KT) asm volatile("cp.async.wait_group 1;\n");
        else             asm volatile("cp.async.wait_group 0;\n");
        __syncthreads();
        if (kt + 2 < KT) {
            const int nb = (kt + 2) % 3;
            LOAD_A(kt + 2, nb); LOAD_B(kt + 2, nb); CP_COMMIT();
        }

        const __half* As = As0 + buf * 8192;
        const __half* Bs = Bs0 + buf * 8192;
#pragma unroll
        for (int kk = 0; kk < 64; kk += 16) {
            uint32_t a[2][4];
#pragma unroll
            for (int i = 0; i < 2; i++) {
                int row = wm + 16 * i + (lane & 15);
                int kc = (kk >> 3) + ((lane & 16) ? 1 : 0);
                uint32_t addr = (uint32_t)__cvta_generic_to_shared(
                    As + row * 64 + ((kc ^ (row & 7)) << 3));
                asm volatile("ldmatrix.sync.aligned.m8n8.x4.shared.b16 {%0,%1,%2,%3}, [%4];\n"
                             : "=r"(a[i][0]), "=r"(a[i][1]), "=r"(a[i][2]), "=r"(a[i][3])
                             : "r"(addr));
            }
            uint32_t b[8][2];
            if (!BNN) {
#pragma unroll
                for (int l = 0; l < 4; l++) {
                    int row = wn + 16 * l + (lane & 7) + ((lane & 16) ? 8 : 0);
                    int kc = (kk >> 3) + ((lane & 8) ? 1 : 0);
                    uint32_t addr = (uint32_t)__cvta_generic_to_shared(
                        Bs + row * 64 + ((kc ^ (row & 7)) << 3));
                    asm volatile("ldmatrix.sync.aligned.m8n8.x4.shared.b16 {%0,%1,%2,%3}, [%4];\n"
                                 : "=r"(b[2 * l][0]), "=r"(b[2 * l][1]),
                                   "=r"(b[2 * l + 1][0]), "=r"(b[2 * l + 1][1])
                                 : "r"(addr));
                }
            } else {
#pragma unroll
                for (int l = 0; l < 4; l++) {
                    int row = kk + (lane & 7) + ((lane & 8) ? 8 : 0);
                    int cc = ((wn + 16 * l) >> 3) + ((lane & 16) ? 1 : 0);
                    int pc = (cc & 8) | ((cc & 7) ^ (row & 7));
                    uint32_t addr = (uint32_t)__cvta_generic_to_shared(
                        Bs + row * 128 + (pc << 3));
                    asm volatile("ldmatrix.sync.aligned.m8n8.x4.trans.shared.b16 {%0,%1,%2,%3}, [%4];\n"
                                 : "=r"(b[2 * l][0]), "=r"(b[2 * l][1]),
                                   "=r"(b[2 * l + 1][0]), "=r"(b[2 * l + 1][1])
                                 : "r"(addr));
                }
            }
#pragma unroll
            for (int i = 0; i < 2; i++)
#pragma unroll
                for (int j = 0; j < 8; j++) mma16816(c[i][j], a[i], b[j]);
        }
    }
#undef LOAD_A
#undef LOAD_B
}

// ---------------- fp32 -> fp16 conversion ----------------
__global__ void __launch_bounds__(256) conv_kernel(const float* __restrict__ src,
                                                   __half* __restrict__ dst) {
    size_t i = ((size_t)blockIdx.x * 256 + threadIdx.x) * 8;
    float4 v0 = *(const float4*)(src + i);
    float4 v1 = *(const float4*)(src + i + 4);
    uint4 o;
    o.x = h2_as_u32(__floats2half2_rn(v0.x, v0.y));
    o.y = h2_as_u32(__floats2half2_rn(v0.z, v0.w));
    o.z = h2_as_u32(__floats2half2_rn(v1.x, v1.y));
    o.w = h2_as_u32(__floats2half2_rn(v1.z, v1.w));
    *(uint4*)(dst + i) = o;
}

// ---------------- zero row sums ----------------
__global__ void __launch_bounds__(256) zero_kernel() {
    g_rowsum[blockIdx.x * 256 + threadIdx.x] = 0.0f;
}

// ---------------- projection: g_outh = g_inh @ W^T + bias ----------------
__global__ void __launch_bounds__(256, 2) proj_kernel(const float* __restrict__ bias) {
    extern __shared__ __half sm[];
    const int m0 = blockIdx.y * BM, n0 = blockIdx.x * BN;
    float c[2][8][4] = {};
    gemm_main<0>(g_inh, g_wh, EDIM, EDIM, m0, n0, EDIM / BK, sm, c);

    const int lane = threadIdx.x & 31, warp = threadIdx.x >> 5;
    const int wm = (warp & 3) * 32, wn = (warp >> 2) * 64;
    const int g = lane >> 2, t = lane & 3;
#pragma unroll
    for (int i = 0; i < 2; i++)
#pragma unroll
        for (int j = 0; j < 8; j++) {
            int row = m0 + wm + 16 * i + g;
            int col = n0 + wn + 8 * j + 2 * t;
            float b0 = bias[col], b1 = bias[col + 1];
            *(__half2*)(g_outh + (size_t)row * PDIM + col) =
                __floats2half2_rn(c[i][j][0] + b0, c[i][j][1] + b1);
            *(__half2*)(g_outh + (size_t)(row + 8) * PDIM + col) =
                __floats2half2_rn(c[i][j][2] + b0, c[i][j][3] + b1);
        }
}

// ---------------- scores+exp: g_probs = exp((Qp @ Kp^T)/32), rowsum atomics --------
__global__ void __launch_bounds__(256, 2) scores_kernel() {
    extern __shared__ __half sm[];
    const size_t z = blockIdx.z;
    const __half* A = g_outh + z * S1D * PDIM;
    const __half* B = g_outh + (size_t)BATCH * S1D * PDIM + z * S2D * PDIM;
    __half* C = g_probs + z * S1D * S2D;
    const int m0 = blockIdx.y * BM, n0 = blockIdx.x * BN;
    float c[2][8][4] = {};
    gemm_main<0>(A, B, PDIM, PDIM, m0, n0, PDIM / BK, sm, c);

    const int lane = threadIdx.x & 31, warp = threadIdx.x >> 5;
    const int wm = (warp & 3) * 32, wn = (warp >> 2) * 64;
    const int g = lane >> 2, t = lane & 3;
    const float SC = 0.03125f;

    float rs[4] = {0.f, 0.f, 0.f, 0.f};   // rows: wm+g, wm+8+g, wm+16+g, wm+24+g
#pragma unroll
    for (int i = 0; i < 2; i++)
#pragma unroll
        for (int j = 0; j < 8; j++) {
            int row = m0 + wm + 16 * i + g;
            int col = n0 + wn + 8 * j + 2 * t;
            float e0 = __expf(c[i][j][0] * SC), e1 = __expf(c[i][j][1] * SC);
            float e2 = __expf(c[i][j][2] * SC), e3 = __expf(c[i][j][3] * SC);
            rs[2 * i] += e0 + e1;
            rs[2 * i + 1] += e2 + e3;
            *(__half2*)(C + (size_t)row * S2D + col) = __floats2half2_rn(e0, e1);
            *(__half2*)(C + (size_t)(row + 8) * S2D + col) = __floats2half2_rn(e2, e3);
        }

    // reduce across the 4 lanes of each quad (same rows), then one atomic per row
#pragma unroll
    for (int r = 0; r < 4; r++) {
        rs[r] += __shfl_xor_sync(0xffffffffu, rs[r], 1);
        rs[r] += __shfl_xor_sync(0xffffffffu, rs[r], 2);
    }
    if (t == 0) {
        int rbase = (int)(z * S1D) + m0 + wm + g;
#pragma unroll
        for (int r = 0; r < 4; r++)
            atomicAdd(g_rowsum + rbase + 8 * r, rs[r]);
    }
}

// ---------------- output: O = (exp_probs @ Vp) / rowsum  (NN gemm) ----------------
__global__ void __launch_bounds__(256, 2) out_kernel(float* __restrict__ OUT) {
    extern __shared__ __half sm[];
    const size_t z = blockIdx.z;
    const __half* A = g_probs + z * S1D * S2D;
    const __half* B = g_outh + (size_t)2 * BATCH * S1D * PDIM + z * S2D * PDIM;
    float* C = OUT + z * S1D * PDIM;
    const int m0 = blockIdx.y * BM, n0 = blockIdx.x * BN;
    float c[2][8][4] = {};
    gemm_main<1>(A, B, S2D, PDIM, m0, n0, S2D / BK, sm, c);

    const int lane = threadIdx.x & 31, warp = threadIdx.x >> 5;
    const int wm = (warp & 3) * 32, wn = (warp >> 2) * 64;
    const int g = lane >> 2, t = lane & 3;

    const int rbase = (int)(z * S1D) + m0 + wm + g;
    float inv[4];
#pragma unroll
    for (int r = 0; r < 4; r++)
        inv[r] = 1.0f / __ldg(g_rowsum + rbase + 8 * r);

#pragma unroll
    for (int i = 0; i < 2; i++)
#pragma unroll
        for (int j = 0; j < 8; j++) {
            int row = m0 + wm + 16 * i + g;
            int col = n0 + wn + 8 * j + 2 * t;
            *(float2*)(C + (size_t)row * PDIM + col) =
                make_float2(c[i][j][0] * inv[2 * i], c[i][j][1] * inv[2 * i]);
            *(float2*)(C + (size_t)(row + 8) * PDIM + col) =
                make_float2(c[i][j][2] * inv[2 * i + 1], c[i][j][3] * inv[2 * i + 1]);
        }
}

// ---------------- launch ----------------
extern "C" void kernel_launch(void* const* d_in, const int* in_sizes, int n_in,
                              void* d_out, int out_size) {
    const float* q = (const float*)d_in[0];
    const float* k = (const float*)d_in[1];
    const float* v = (const float*)d_in[2];
    const float* W = (const float*)d_in[3];
    const float* b = (const float*)d_in[4];
    float* out = (float*)d_out;

    static bool attr_done = false;
    if (!attr_done) {
        cudaFuncSetAttribute(proj_kernel, cudaFuncAttributeMaxDynamicSharedMemorySize, 98304);
        cudaFuncSetAttribute(scores_kernel, cudaFuncAttributeMaxDynamicSharedMemorySize, 98304);
        cudaFuncSetAttribute(out_kernel, cudaFuncAttributeMaxDynamicSharedMemorySize, 98304);
        attr_done = true;
    }

    __half* inh;
    __half* wh;
    cudaGetSymbolAddress((void**)&inh, g_inh);
    cudaGetSymbolAddress((void**)&wh, g_wh);

    const size_t NT = (size_t)BATCH * S1D * EDIM;  // 16.7M per tensor
    conv_kernel<<<NT / (256 * 8), 256>>>(q, inh);
    conv_kernel<<<NT / (256 * 8), 256>>>(k, inh + NT);
    conv_kernel<<<NT / (256 * 8), 256>>>(v, inh + 2 * NT);
    conv_kernel<<<(PDIM * EDIM) / (256 * 8), 256>>>(W, wh);
    zero_kernel<<<(BATCH * S1D) / 256, 256>>>();

    dim3 gproj(PDIM / BN, (3 * BATCH * S1D) / BM);  // 8 x 384
    proj_kernel<<<gproj, 256, 98304>>>(b);

    dim3 gs(S2D / BN, S1D / BM, BATCH);  // 16 x 16 x 8
    scores_kernel<<<gs, 256, 98304>>>();

    dim3 go(PDIM / BN, S1D / BM, BATCH);  // 8 x 16 x 8
    out_kernel<<<go, 256, 98304>>>(out);
}

// round 12
// speedup vs baseline: 1.0346x; 1.0086x over previous
#include <cuda_runtime.h>
#include <cuda_fp16.h>
#include <cstdint>

#define BATCH 8
#define S1D 2048
#define S2D 2048
#define EDIM 1024
#define PDIM 1024

#define BM 128
#define BN 128
#define BK 64

// ---------------- scratch ----------------
__device__ __half g_inh[(size_t)3 * BATCH * S1D * EDIM];   // q,k,v fp16 (96 MB)
__device__ __half g_outh[(size_t)3 * BATCH * S1D * PDIM];  // projected q,k,v fp16 (96 MB)
__device__ __half g_wh[(size_t)PDIM * EDIM];               // 2 MB
__device__ __half g_probs[(size_t)BATCH * S1D * S2D];      // exp(scores) fp16 (67 MB)
__device__ float  g_rowsum[(size_t)BATCH * S1D];           // 64 KB

__device__ __forceinline__ void mma16816(float c[4], const uint32_t a[4], const uint32_t b[2]) {
    asm volatile(
        "mma.sync.aligned.m16n8k16.row.col.f32.f16.f16.f32 "
        "{%0,%1,%2,%3}, {%4,%5,%6,%7}, {%8,%9}, {%0,%1,%2,%3};\n"
        : "+f"(c[0]), "+f"(c[1]), "+f"(c[2]), "+f"(c[3])
        : "r"(a[0]), "r"(a[1]), "r"(a[2]), "r"(a[3]), "r"(b[0]), "r"(b[1]));
}

__device__ __forceinline__ void cp16(__half* sptr, const __half* gptr) {
    uint32_t s = (uint32_t)__cvta_generic_to_shared(sptr);
    asm volatile("cp.async.cg.shared.global [%0], [%1], 16;\n" :: "r"(s), "l"(gptr));
}
#define CP_COMMIT() asm volatile("cp.async.commit_group;\n")

__device__ __forceinline__ uint32_t h2_as_u32(__half2 h) {
    return *reinterpret_cast<uint32_t*>(&h);
}

// =================================================================================
// GEMM mainloop. Block tile 128x128, BK=64, 4 warps, warp tile 64x64 (warp grid 2x2).
// 3-stage cp.async pipeline, fp32 accumulators c[4][8][4].
// A: [M][K] fp16 k-major. B: NT: [N][K] k-major; NN: [K][N] n-major (ldmatrix.trans).
// Smem swizzle: 16B chunk c at row r placed at chunk (c ^ (r&7)) within 128B span.
// =================================================================================
template<int BNN>
__device__ __forceinline__ void gemm_main(const __half* __restrict__ A,
                                          const __half* __restrict__ B,
                                          int lda, int ldb, int m0, int n0, int KT,
                                          __half* sm, float c[4][8][4]) {
    const int tid = threadIdx.x;
    const int warp = tid >> 5, lane = tid & 31;
    const int wm = (warp & 1) * 64, wn = (warp >> 1) * 64;
    __half* As0 = sm;           // 3 x 8192 halves (16KB/stage)
    __half* Bs0 = sm + 24576;   // 3 x 8192 halves

    const int a_r = tid >> 3, a_c = tid & 7;     // 16 rows/sweep, 8 sweeps (128 rows x 8 chunks)
    const int bn_r = tid >> 4, bn_c = tid & 15;  // NN: 8 rows/sweep, 8 sweeps (64 rows x 16 chunks)

#define LOAD_A(kt, buf) {                                                              \
        __half* S = As0 + (buf) * 8192;                                                \
        _Pragma("unroll")                                                              \
        for (int s = 0; s < 8; s++) {                                                  \
            int r = a_r + 16 * s;                                                      \
            cp16(S + r * 64 + ((a_c ^ (r & 7)) << 3),                                  \
                 A + (size_t)(m0 + r) * lda + (kt) * 64 + a_c * 8);                    \
        } }
#define LOAD_B(kt, buf) {                                                              \
        __half* S = Bs0 + (buf) * 8192;                                                \
        if (!BNN) {                                                                    \
            _Pragma("unroll")                                                          \
            for (int s = 0; s < 8; s++) {                                              \
                int r = a_r + 16 * s;                                                  \
                cp16(S + r * 64 + ((a_c ^ (r & 7)) << 3),                              \
                     B + (size_t)(n0 + r) * ldb + (kt) * 64 + a_c * 8);                \
            }                                                                          \
        } else {                                                                       \
            _Pragma("unroll")                                                          \
            for (int s = 0; s < 8; s++) {                                              \
                int r = bn_r + 8 * s;                                                  \
                int pc = (bn_c & 8) | ((bn_c & 7) ^ (r & 7));                          \
                cp16(S + r * 128 + (pc << 3),                                          \
                     B + (size_t)((kt) * 64 + r) * ldb + n0 + bn_c * 8);               \
            }                                                                          \
        } }

    LOAD_A(0, 0); LOAD_B(0, 0); CP_COMMIT();
    LOAD_A(1, 1); LOAD_B(1, 1); CP_COMMIT();

    for (int kt = 0; kt < KT; kt++) {
        const int buf = kt % 3;
        if (kt + 1 < KT) asm volatile("cp.async.wait_group 1;\n");
        else             asm volatile("cp.async.wait_group 0;\n");
        __syncthreads();
        if (kt + 2 < KT) {
            const int nb = (kt + 2) % 3;
            LOAD_A(kt + 2, nb); LOAD_B(kt + 2, nb); CP_COMMIT();
        }

        const __half* As = As0 + buf * 8192;
        const __half* Bs = Bs0 + buf * 8192;
#pragma unroll
        for (int kk = 0; kk < 64; kk += 16) {
            uint32_t a[4][4];
#pragma unroll
            for (int i = 0; i < 4; i++) {
                int row = wm + 16 * i + (lane & 15);
                int kc = (kk >> 3) + ((lane & 16) ? 1 : 0);
                uint32_t addr = (uint32_t)__cvta_generic_to_shared(
                    As + row * 64 + ((kc ^ (row & 7)) << 3));
                asm volatile("ldmatrix.sync.aligned.m8n8.x4.shared.b16 {%0,%1,%2,%3}, [%4];\n"
                             : "=r"(a[i][0]), "=r"(a[i][1]), "=r"(a[i][2]), "=r"(a[i][3])
                             : "r"(addr));
            }
            uint32_t b[8][2];
            if (!BNN) {
#pragma unroll
                for (int l = 0; l < 4; l++) {
                    int row = wn + 16 * l + (lane & 7) + ((lane & 16) ? 8 : 0);
                    int kc = (kk >> 3) + ((lane & 8) ? 1 : 0);
                    uint32_t addr = (uint32_t)__cvta_generic_to_shared(
                        Bs + row * 64 + ((kc ^ (row & 7)) << 3));
                    asm volatile("ldmatrix.sync.aligned.m8n8.x4.shared.b16 {%0,%1,%2,%3}, [%4];\n"
                                 : "=r"(b[2 * l][0]), "=r"(b[2 * l][1]),
                                   "=r"(b[2 * l + 1][0]), "=r"(b[2 * l + 1][1])
                                 : "r"(addr));
                }
            } else {
#pragma unroll
                for (int l = 0; l < 4; l++) {
                    int row = kk + (lane & 7) + ((lane & 8) ? 8 : 0);
                    int cc = ((wn + 16 * l) >> 3) + ((lane & 16) ? 1 : 0);
                    int pc = (cc & 8) | ((cc & 7) ^ (row & 7));
                    uint32_t addr = (uint32_t)__cvta_generic_to_shared(
                        Bs + row * 128 + (pc << 3));
                    asm volatile("ldmatrix.sync.aligned.m8n8.x4.trans.shared.b16 {%0,%1,%2,%3}, [%4];\n"
                                 : "=r"(b[2 * l][0]), "=r"(b[2 * l][1]),
                                   "=r"(b[2 * l + 1][0]), "=r"(b[2 * l + 1][1])
                                 : "r"(addr));
                }
            }
#pragma unroll
            for (int i = 0; i < 4; i++)
#pragma unroll
                for (int j = 0; j < 8; j++) mma16816(c[i][j], a[i], b[j]);
        }
    }
#undef LOAD_A
#undef LOAD_B
}

// ---------------- fp32 -> fp16 conversion ----------------
__global__ void __launch_bounds__(256) conv_kernel(const float* __restrict__ src,
                                                   __half* __restrict__ dst) {
    size_t i = ((size_t)blockIdx.x * 256 + threadIdx.x) * 8;
    float4 v0 = *(const float4*)(src + i);
    float4 v1 = *(const float4*)(src + i + 4);
    uint4 o;
    o.x = h2_as_u32(__floats2half2_rn(v0.x, v0.y));
    o.y = h2_as_u32(__floats2half2_rn(v0.z, v0.w));
    o.z = h2_as_u32(__floats2half2_rn(v1.x, v1.y));
    o.w = h2_as_u32(__floats2half2_rn(v1.z, v1.w));
    *(uint4*)(dst + i) = o;
}

// ---------------- zero row sums ----------------
__global__ void __launch_bounds__(256) zero_kernel() {
    g_rowsum[blockIdx.x * 256 + threadIdx.x] = 0.0f;
}

// ---------------- projection: g_outh = g_inh @ W^T + bias ----------------
__global__ void __launch_bounds__(128, 2) proj_kernel(const float* __restrict__ bias) {
    extern __shared__ __half sm[];
    const int m0 = blockIdx.y * BM, n0 = blockIdx.x * BN;
    float c[4][8][4] = {};
    gemm_main<0>(g_inh, g_wh, EDIM, EDIM, m0, n0, EDIM / BK, sm, c);

    const int lane = threadIdx.x & 31, warp = threadIdx.x >> 5;
    const int wm = (warp & 1) * 64, wn = (warp >> 1) * 64;
    const int g = lane >> 2, t = lane & 3;
#pragma unroll
    for (int i = 0; i < 4; i++)
#pragma unroll
        for (int j = 0; j < 8; j++) {
            int row = m0 + wm + 16 * i + g;
            int col = n0 + wn + 8 * j + 2 * t;
            float b0 = bias[col], b1 = bias[col + 1];
            *(__half2*)(g_outh + (size_t)row * PDIM + col) =
                __floats2half2_rn(c[i][j][0] + b0, c[i][j][1] + b1);
            *(__half2*)(g_outh + (size_t)(row + 8) * PDIM + col) =
                __floats2half2_rn(c[i][j][2] + b0, c[i][j][3] + b1);
        }
}

// ---------------- scores+exp: g_probs = exp((Qp @ Kp^T)/32), rowsum atomics --------
__global__ void __launch_bounds__(128, 2) scores_kernel() {
    extern __shared__ __half sm[];
    const size_t z = blockIdx.z;
    const __half* A = g_outh + z * S1D * PDIM;
    const __half* B = g_outh + (size_t)BATCH * S1D * PDIM + z * S2D * PDIM;
    __half* C = g_probs + z * S1D * S2D;
    const int m0 = blockIdx.y * BM, n0 = blockIdx.x * BN;
    float c[4][8][4] = {};
    gemm_main<0>(A, B, PDIM, PDIM, m0, n0, PDIM / BK, sm, c);

    const int lane = threadIdx.x & 31, warp = threadIdx.x >> 5;
    const int wm = (warp & 1) * 64, wn = (warp >> 1) * 64;
    const int g = lane >> 2, t = lane & 3;
    const float SC = 0.03125f;

    float rs[8] = {0.f, 0.f, 0.f, 0.f, 0.f, 0.f, 0.f, 0.f};  // rows wm+16i+g, wm+16i+8+g
#pragma unroll
    for (int i = 0; i < 4; i++)
#pragma unroll
        for (int j = 0; j < 8; j++) {
            int row = m0 + wm + 16 * i + g;
            int col = n0 + wn + 8 * j + 2 * t;
            float e0 = __expf(c[i][j][0] * SC), e1 = __expf(c[i][j][1] * SC);
            float e2 = __expf(c[i][j][2] * SC), e3 = __expf(c[i][j][3] * SC);
            rs[2 * i] += e0 + e1;
            rs[2 * i + 1] += e2 + e3;
            *(__half2*)(C + (size_t)row * S2D + col) = __floats2half2_rn(e0, e1);
            *(__half2*)(C + (size_t)(row + 8) * S2D + col) = __floats2half2_rn(e2, e3);
        }

    // reduce across the 4 lanes of each quad (same rows), then one atomic per row
#pragma unroll
    for (int r = 0; r < 8; r++) {
        rs[r] += __shfl_xor_sync(0xffffffffu, rs[r], 1);
        rs[r] += __shfl_xor_sync(0xffffffffu, rs[r], 2);
    }
    if (t == 0) {
        int rbase = (int)(z * S1D) + m0 + wm + g;
#pragma unroll
        for (int i = 0; i < 4; i++) {
            atomicAdd(g_rowsum + rbase + 16 * i, rs[2 * i]);
            atomicAdd(g_rowsum + rbase + 16 * i + 8, rs[2 * i + 1]);
        }
    }
}

// ---------------- output: O = (exp_probs @ Vp) / rowsum  (NN gemm) ----------------
__global__ void __launch_bounds__(128, 2) out_kernel(float* __restrict__ OUT) {
    extern __shared__ __half sm[];
    const size_t z = blockIdx.z;
    const __half* A = g_probs + z * S1D * S2D;
    const __half* B = g_outh + (size_t)2 * BATCH * S1D * PDIM + z * S2D * PDIM;
    float* C = OUT + z * S1D * PDIM;
    const int m0 = blockIdx.y * BM, n0 = blockIdx.x * BN;
    float c[4][8][4] = {};
    gemm_main<1>(A, B, S2D, PDIM, m0, n0, S2D / BK, sm, c);

    const int lane = threadIdx.x & 31, warp = threadIdx.x >> 5;
    const int wm = (warp & 1) * 64, wn = (warp >> 1) * 64;
    const int g = lane >> 2, t = lane & 3;

    const int rbase = (int)(z * S1D) + m0 + wm + g;
    float inv[8];
#pragma unroll
    for (int i = 0; i < 4; i++) {
        inv[2 * i] = 1.0f / __ldg(g_rowsum + rbase + 16 * i);
        inv[2 * i + 1] = 1.0f / __ldg(g_rowsum + rbase + 16 * i + 8);
    }

#pragma unroll
    for (int i = 0; i < 4; i++)
#pragma unroll
        for (int j = 0; j < 8; j++) {
            int row = m0 + wm + 16 * i + g;
            int col = n0 + wn + 8 * j + 2 * t;
            *(float2*)(C + (size_t)row * PDIM + col) =
                make_float2(c[i][j][0] * inv[2 * i], c[i][j][1] * inv[2 * i]);
            *(float2*)(C + (size_t)(row + 8) * PDIM + col) =
                make_float2(c[i][j][2] * inv[2 * i + 1], c[i][j][3] * inv[2 * i + 1]);
        }
}

// ---------------- launch ----------------
extern "C" void kernel_launch(void* const* d_in, const int* in_sizes, int n_in,
                              void* d_out, int out_size) {
    const float* q = (const float*)d_in[0];
    const float* k = (const float*)d_in[1];
    const float* v = (const float*)d_in[2];
    const float* W = (const float*)d_in[3];
    const float* b = (const float*)d_in[4];
    float* out = (float*)d_out;

    static bool attr_done = false;
    if (!attr_done) {
        cudaFuncSetAttribute(proj_kernel, cudaFuncAttributeMaxDynamicSharedMemorySize, 98304);
        cudaFuncSetAttribute(scores_kernel, cudaFuncAttributeMaxDynamicSharedMemorySize, 98304);
        cudaFuncSetAttribute(out_kernel, cudaFuncAttributeMaxDynamicSharedMemorySize, 98304);
        attr_done = true;
    }

    __half* inh;
    __half* wh;
    cudaGetSymbolAddress((void**)&inh, g_inh);
    cudaGetSymbolAddress((void**)&wh, g_wh);

    const size_t NT = (size_t)BATCH * S1D * EDIM;  // 16.7M per tensor
    conv_kernel<<<NT / (256 * 8), 256>>>(q, inh);
    conv_kernel<<<NT / (256 * 8), 256>>>(k, inh + NT);
    conv_kernel<<<NT / (256 * 8), 256>>>(v, inh + 2 * NT);
    conv_kernel<<<(PDIM * EDIM) / (256 * 8), 256>>>(W, wh);
    zero_kernel<<<(BATCH * S1D) / 256, 256>>>();

    dim3 gproj(PDIM / BN, (3 * BATCH * S1D) / BM);  // 8 x 384
    proj_kernel<<<gproj, 128, 98304>>>(b);

    dim3 gs(S2D / BN, S1D / BM, BATCH);  // 16 x 16 x 8
    scores_kernel<<<gs, 128, 98304>>>();

    dim3 go(PDIM / BN, S1D / BM, BATCH);  // 8 x 16 x 8
    out_kernel<<<go, 128, 98304>>>(out);
}